// round 7
// baseline (speedup 1.0000x reference)
#include <cuda_runtime.h>
#include <cuda_bf16.h>
#include <cstdint>

// ---------------------------------------------------------------------------
// Problem constants
// ---------------------------------------------------------------------------
#define B_    128
#define S_    256
#define L_    200
#define D_    768
#define POSD  50
#define FEAT  818
#define REDUC 400
#define HID   150
#define PROJN 600
#define TAGS  5
#define POL   4
#define M_    25600

// K paddings (chunks of 64 bf16); buffers hold [hi(Kp) | lo(Kp)] per row
#define KP_H   832   // FEAT=818 -> T=13
#define KP_R   448   // REDUC=400 -> T=7
#define KP_N   192   // HID=150 -> T=3

// ---------------------------------------------------------------------------
// Scratch
// ---------------------------------------------------------------------------
__device__ __align__(128) __nv_bfloat16 g_hbf[(long)M_ * 2 * KP_H];
__device__ __align__(128) __nv_bfloat16 g_Wr_bf[(long)REDUC * 2 * KP_H];
__device__ __align__(128) __nv_bfloat16 g_reduc_bf[(long)M_ * 2 * KP_R];
__device__ float g_WprojF[PROJN * REDUC];
__device__ __align__(128) __nv_bfloat16 g_Wp_bf[(long)PROJN * 2 * KP_R];
__device__ float g_bproj[PROJN];
__device__ float g_bbi[PROJN];
__device__ float g_proj[(long)M_ * PROJN];   // only cols [0,300) written/used (tag heads)
__device__ __align__(128) __nv_bfloat16 g_apn_bf[(long)M_ * 2 * KP_N];
__device__ __align__(128) __nv_bfloat16 g_opn_bf[(long)M_ * 2 * KP_N];
__device__ __align__(128) __nv_bfloat16 g_Wbi_bf[(long)PROJN * 2 * KP_N];
__device__ __align__(128) __nv_bfloat16 g_aff_bf[(long)B_ * 800 * 2 * KP_N];

// ---------------------------------------------------------------------------
// PTX helpers (family-common only: cp.async / ldmatrix / mma.sync)
// ---------------------------------------------------------------------------
__device__ __forceinline__ uint32_t smem_u32(const void* p) {
    uint32_t a;
    asm("{ .reg .u64 t; cvta.to.shared.u64 t, %1; cvt.u32.u64 %0, t; }" : "=r"(a) : "l"(p));
    return a;
}
__device__ __forceinline__ void cp_async16(uint32_t dst, const void* src, int sz) {
    asm volatile("cp.async.cg.shared.global [%0], [%1], 16, %2;"
                 :: "r"(dst), "l"(src), "r"(sz) : "memory");
}
#define CP_COMMIT() asm volatile("cp.async.commit_group;" ::: "memory")
#define CP_WAIT(n)  asm volatile("cp.async.wait_group %0;" :: "n"(n) : "memory")

__device__ __forceinline__ uint32_t swz(uint32_t off) {
    return off ^ ((off >> 3) & 0x70);
}
__device__ __forceinline__ void ldsm_x4(uint32_t* r, uint32_t addr) {
    asm volatile("ldmatrix.sync.aligned.m8n8.x4.shared.b16 {%0,%1,%2,%3}, [%4];"
                 : "=r"(r[0]), "=r"(r[1]), "=r"(r[2]), "=r"(r[3]) : "r"(addr));
}
__device__ __forceinline__ void ldsm_x2(uint32_t* r, uint32_t addr) {
    asm volatile("ldmatrix.sync.aligned.m8n8.x2.shared.b16 {%0,%1}, [%2];"
                 : "=r"(r[0]), "=r"(r[1]) : "r"(addr));
}
__device__ __forceinline__ void mma_bf16(float* c, const uint32_t* a, const uint32_t* b) {
    asm volatile(
        "mma.sync.aligned.m16n8k16.row.col.f32.bf16.bf16.f32 "
        "{%0,%1,%2,%3}, {%4,%5,%6,%7}, {%8,%9}, {%0,%1,%2,%3};"
        : "+f"(c[0]), "+f"(c[1]), "+f"(c[2]), "+f"(c[3])
        : "r"(a[0]), "r"(a[1]), "r"(a[2]), "r"(a[3]), "r"(b[0]), "r"(b[1]));
}
__device__ __forceinline__ void put_split(__nv_bfloat16* S, long row, int k, int Kp, float v) {
    __nv_bfloat16 hi = __float2bfloat16(v);
    float lo = v - __bfloat162float(hi);
    S[row * (long)(2 * Kp) + k]      = hi;
    S[row * (long)(2 * Kp) + Kp + k] = __float2bfloat16(lo);
}

// ---------------------------------------------------------------------------
// mma.sync split-bf16 GEMM, CTA 128x128, BK=64, 3-stage cp.async pipeline.
// Epilogue variants (EPI):
//   0: fp32 C only                         (triplet -> d_out)
//   1: split-bf16 S0 (row=m, k=n)          (reduc)
//   2: fp32 C for n<300; S0 k=n-300 for n in [300,450); S1 k=n-450 for [450,600)
//   3: split-bf16 S0, row = m*4 + n/150, k = n%150   (affine)
// ---------------------------------------------------------------------------
#define SMEM_BYTES 98304

template<int EPI>
__global__ __launch_bounds__(256, 2)
void gemm_mma(const __nv_bfloat16* __restrict__ A, int lda, long sA, int Mrows,
              const __nv_bfloat16* __restrict__ Bw, int ldb, long sB, int Nrows,
              const float* __restrict__ bias,
              float* __restrict__ Cf, int ldc, long sC,
              __nv_bfloat16* __restrict__ S0, __nv_bfloat16* __restrict__ S1,
              int Kp, int T, int relu)
{
    extern __shared__ char smem[];
    const uint32_t sbase = smem_u32(smem);
    const int tid = threadIdx.x, wid = tid >> 5, lane = tid & 31;
    const int m0 = blockIdx.y * 128;
    const int n0 = blockIdx.x * 128;
    A  += (long)blockIdx.z * sA;
    Bw += (long)blockIdx.z * sB;
    if (Cf) Cf += (long)blockIdx.z * sC;
    const int NT = 3 * T;

    const int wm = wid & 1;        // 0..1 : M quadrant (64 rows)
    const int wn = wid >> 1;       // 0..3 : N quadrant (32 cols)

    float acc[4][4][4];
#pragma unroll
    for (int i = 0; i < 4; i++)
#pragma unroll
        for (int j = 0; j < 4; j++)
#pragma unroll
            for (int k = 0; k < 4; k++) acc[i][j][k] = 0.0f;

    auto load_stage = [&](int t, int buf) {
        const int ka = (t < T) ? t : t - T;            // A: hi, hi, lo
        const int kb = (t < 2 * T) ? t : t - 2 * T;    // B: hi, lo, hi
        const uint32_t abase = sbase + (uint32_t)buf * 32768u;
        const uint32_t bbase = abase + 16384u;
#pragma unroll
        for (int i = 0; i < 4; i++) {
            int idx = i * 256 + tid;            // 0..1023
            int r = idx >> 3, c = idx & 7;
            int gm = m0 + r;
            int ok = (gm < Mrows);
            const char* src = (const char*)(A + (long)(ok ? gm : 0) * lda + (long)ka * 64) + c * 16;
            cp_async16(abase + swz((uint32_t)(r * 128 + c * 16)), src, ok ? 16 : 0);
        }
#pragma unroll
        for (int i = 0; i < 4; i++) {
            int idx = i * 256 + tid;
            int r = idx >> 3, c = idx & 7;
            int gn = n0 + r;
            int ok = (gn < Nrows);
            const char* src = (const char*)(Bw + (long)(ok ? gn : 0) * ldb + (long)kb * 64) + c * 16;
            cp_async16(bbase + swz((uint32_t)(r * 128 + c * 16)), src, ok ? 16 : 0);
        }
        CP_COMMIT();
    };

    load_stage(0, 0);
    load_stage(1, 1);

    int buf = 0;
    for (int t = 0; t < NT; t++) {
        CP_WAIT(1);
        __syncthreads();
        if (t + 2 < NT) {
            int nb = buf + 2; if (nb >= 3) nb -= 3;
            load_stage(t + 2, nb);
        }
        const uint32_t abase = sbase + (uint32_t)buf * 32768u;
        const uint32_t bbase = abase + 16384u;
#pragma unroll
        for (int ks = 0; ks < 4; ks++) {
            uint32_t ra[4][4], rb[4][2];
#pragma unroll
            for (int mi = 0; mi < 4; mi++) {
                int row = wm * 64 + mi * 16 + (lane & 15);
                uint32_t off = (uint32_t)(row * 128 + ks * 32 + (lane >> 4) * 16);
                ldsm_x4(ra[mi], abase + swz(off));
            }
#pragma unroll
            for (int ni = 0; ni < 4; ni++) {
                int l16 = lane & 15;
                int row = wn * 32 + ni * 8 + (l16 & 7);
                uint32_t off = (uint32_t)(row * 128 + ks * 32 + ((l16 >> 3) & 1) * 16);
                ldsm_x2(rb[ni], bbase + swz(off));
            }
#pragma unroll
            for (int mi = 0; mi < 4; mi++)
#pragma unroll
                for (int ni = 0; ni < 4; ni++)
                    mma_bf16(acc[mi][ni], ra[mi], rb[ni]);
        }
        buf++; if (buf >= 3) buf = 0;
    }

    // epilogue: fragment layout c0:(r,c) c1:(r,c+1) c2:(r+8,c) c3:(r+8,c+1)
#pragma unroll
    for (int mi = 0; mi < 4; mi++) {
        int rb0 = m0 + wm * 64 + mi * 16 + (lane >> 2);
#pragma unroll
        for (int ni = 0; ni < 4; ni++) {
            int cb = n0 + wn * 32 + ni * 8 + (lane & 3) * 2;
#pragma unroll
            for (int half = 0; half < 2; half++) {
                int gm = rb0 + half * 8;
                if (gm >= Mrows) continue;
#pragma unroll
                for (int e = 0; e < 2; e++) {
                    int gn = cb + e;
                    if (gn >= Nrows) continue;
                    float v = acc[mi][ni][half * 2 + e];
                    if (bias) v += bias[gn];
                    if (relu) v = fmaxf(v, 0.0f);
                    if constexpr (EPI == 0) {
                        Cf[(long)gm * ldc + gn] = v;
                    } else if constexpr (EPI == 1) {
                        put_split(S0, gm, gn, Kp, v);
                    } else if constexpr (EPI == 2) {
                        if (gn < 300) {
                            Cf[(long)gm * ldc + gn] = v;
                        } else if (gn < 450) {
                            put_split(S0, gm, gn - 300, Kp, v);
                        } else {
                            put_split(S1, gm, gn - 450, Kp, v);
                        }
                    } else {  // EPI == 3
                        int p = gn / 150, k = gn - p * 150;
                        put_split(S0, (long)gm * 4 + p, k, Kp, v);
                    }
                }
            }
        }
    }
}

// ---------------------------------------------------------------------------
// Zero the K-padding lanes of the epilogue-written split buffers (each run,
// for graph-replay determinism). hi and lo halves both zeroed.
// ---------------------------------------------------------------------------
__global__ void zero_pads()
{
    const __nv_bfloat16 z = __float2bfloat16(0.0f);
    long i = (long)blockIdx.x * blockDim.x + threadIdx.x;
    const long n1 = (long)M_ * 48;        // reduc_bf k in [400,448)
    const long n2 = (long)M_ * 42;        // apn_bf  k in [150,192)
    const long n3 = (long)M_ * 42;        // opn_bf
    const long n4 = (long)B_ * 800 * 42;  // aff_bf
    if (i < n1) {
        long r = i / 48; int k = 400 + (int)(i % 48);
        g_reduc_bf[r * (2 * KP_R) + k] = z;
        g_reduc_bf[r * (2 * KP_R) + KP_R + k] = z;
        return;
    }
    i -= n1;
    if (i < n2) {
        long r = i / 42; int k = 150 + (int)(i % 42);
        g_apn_bf[r * (2 * KP_N) + k] = z;
        g_apn_bf[r * (2 * KP_N) + KP_N + k] = z;
        return;
    }
    i -= n2;
    if (i < n3) {
        long r = i / 42; int k = 150 + (int)(i % 42);
        g_opn_bf[r * (2 * KP_N) + k] = z;
        g_opn_bf[r * (2 * KP_N) + KP_N + k] = z;
        return;
    }
    i -= n3;
    if (i < n4) {
        long r = i / 42; int k = 150 + (int)(i % 42);
        g_aff_bf[r * (2 * KP_N) + k] = z;
        g_aff_bf[r * (2 * KP_N) + KP_N + k] = z;
    }
}

// ---------------------------------------------------------------------------
// Prep: concat projection weights (fp32), biases, biaffine bias column
// ---------------------------------------------------------------------------
__global__ void prep_kernel(const float* __restrict__ Wap, const float* __restrict__ bap,
                            const float* __restrict__ Wop, const float* __restrict__ bop,
                            const float* __restrict__ Wap2, const float* __restrict__ bap2,
                            const float* __restrict__ Wop2, const float* __restrict__ bop2,
                            const float* __restrict__ Wbi)
{
    int i = blockIdx.x * blockDim.x + threadIdx.x;
    if (i < PROJN * REDUC) {
        int n = i / REDUC, k = i % REDUC;
        const float* src = (n < 150) ? Wap : (n < 300) ? Wop : (n < 450) ? Wap2 : Wop2;
        g_WprojF[i] = src[(n % 150) * REDUC + k];
    }
    if (i < PROJN) {
        const float* sb = (i < 150) ? bap : (i < 300) ? bop : (i < 450) ? bap2 : bop2;
        g_bproj[i] = sb[i % 150];
        g_bbi[i]   = Wbi[i * 151 + 150];
    }
}

// ---------------------------------------------------------------------------
// Split fp32 -> [hi|lo] bf16 rows (weights only; grid.x = row)
// ---------------------------------------------------------------------------
__global__ void conv_split(const float* __restrict__ src, int sld, int soff,
                           __nv_bfloat16* __restrict__ dst, int Kp, int K)
{
    long r = blockIdx.x;
    const float* s = src + r * (long)sld + soff;
    __nv_bfloat16* d = dst + r * (long)(2 * Kp);
    for (int k = threadIdx.x; k < Kp; k += blockDim.x) {
        float v = (k < K) ? s[k] : 0.0f;
        __nv_bfloat16 hi = __float2bfloat16(v);
        float lo = v - __bfloat162float(hi);
        d[k]      = hi;
        d[Kp + k] = __float2bfloat16(lo);
    }
}

// ---------------------------------------------------------------------------
// Pool subwords + POS embed, writing split-bf16 h directly [m, 2*KP_H]
// ---------------------------------------------------------------------------
__global__ void pool_embed_bf(const float* __restrict__ bert,
                              const int* __restrict__ positions,
                              const int* __restrict__ postag,
                              const float* __restrict__ embed)
{
    int m = blockIdx.x;
    int b = m / L_;
    __shared__ int s_start, s_end, s_tag;
    if (threadIdx.x == 0) {
        s_start = positions[m * 2 + 0];
        s_end   = positions[m * 2 + 1];
        s_tag   = postag[m];
    }
    __syncthreads();
    const int start = s_start, end = s_end, tag = s_tag;
    const float inv = 1.0f / (float)(end - start + 1);
    const float* bb = bert + (long)b * S_ * D_;
    __nv_bfloat16* hrow = g_hbf + (long)m * 2 * KP_H;
    for (int f = threadIdx.x; f < KP_H; f += blockDim.x) {
        float v = 0.0f;
        if (f < POSD) {
            v = embed[tag * POSD + f];
        } else if (f < FEAT) {
            int d = f - POSD;
            float s = 0.0f;
            for (int si = start; si <= end; si++) s += bb[(long)si * D_ + d];
            v = s * inv;
        }
        __nv_bfloat16 hi = __float2bfloat16(v);
        float lo = v - __bfloat162float(hi);
        hrow[f]        = hi;
        hrow[KP_H + f] = __float2bfloat16(lo);
    }
}

// ---------------------------------------------------------------------------
// Tag heads (fp32, tiny) -- reads g_proj cols [0,300)
// ---------------------------------------------------------------------------
__global__ void tag_kernel(const float* __restrict__ Wap, const float* __restrict__ bap,
                           const float* __restrict__ Wop, const float* __restrict__ bop,
                           float* __restrict__ out)
{
    int i = blockIdx.x * blockDim.x + threadIdx.x;
    if (i >= M_ * 2 * TAGS) return;
    int m = i / (2 * TAGS);
    int r = i % (2 * TAGS);
    int t = r % TAGS;
    bool is_op = (r >= TAGS);
    const float* a = g_proj + (long)m * PROJN + (is_op ? 150 : 0);
    const float* w = (is_op ? Wop : Wap) + t * HID;
    float s = (is_op ? bop : bap)[t];
#pragma unroll 5
    for (int k = 0; k < HID; k++) s += a[k] * w[k];
    out[(is_op ? (long)M_ * TAGS : 0l) + (long)m * TAGS + t] = s;
}

// ---------------------------------------------------------------------------
// kernel_launch
// ---------------------------------------------------------------------------
template <typename T_>
static T_* sym_addr(const void* symbol) {
    void* p = nullptr;
    cudaGetSymbolAddress(&p, symbol);
    return (T_*)p;
}

extern "C" void kernel_launch(void* const* d_in, const int* in_sizes, int n_in,
                              void* d_out, int out_size)
{
    const float* bert      = (const float*)d_in[0];
    const int*   positions = (const int*)  d_in[1];
    const int*   postag    = (const int*)  d_in[2];
    const float* embed     = (const float*)d_in[3];
    const float* W_reduc   = (const float*)d_in[4];
    const float* b_reduc   = (const float*)d_in[5];
    const float* W_ap      = (const float*)d_in[6];
    const float* b_ap      = (const float*)d_in[7];
    const float* W_op      = (const float*)d_in[8];
    const float* b_op      = (const float*)d_in[9];
    const float* W_ap2     = (const float*)d_in[10];
    const float* b_ap2     = (const float*)d_in[11];
    const float* W_op2     = (const float*)d_in[12];
    const float* b_op2     = (const float*)d_in[13];
    const float* W_aptag   = (const float*)d_in[14];
    const float* b_aptag   = (const float*)d_in[15];
    const float* W_optag   = (const float*)d_in[16];
    const float* b_optag   = (const float*)d_in[17];
    const float* W_bi      = (const float*)d_in[18];
    float* out = (float*)d_out;

    __nv_bfloat16* p_hbf      = sym_addr<__nv_bfloat16>(g_hbf);
    __nv_bfloat16* p_Wr_bf    = sym_addr<__nv_bfloat16>(g_Wr_bf);
    __nv_bfloat16* p_reduc_bf = sym_addr<__nv_bfloat16>(g_reduc_bf);
    float*         p_WprojF   = sym_addr<float>(g_WprojF);
    __nv_bfloat16* p_Wp_bf    = sym_addr<__nv_bfloat16>(g_Wp_bf);
    float*         p_bproj    = sym_addr<float>(g_bproj);
    float*         p_bbi      = sym_addr<float>(g_bbi);
    float*         p_proj     = sym_addr<float>(g_proj);
    __nv_bfloat16* p_apn_bf   = sym_addr<__nv_bfloat16>(g_apn_bf);
    __nv_bfloat16* p_opn_bf   = sym_addr<__nv_bfloat16>(g_opn_bf);
    __nv_bfloat16* p_Wbi_bf   = sym_addr<__nv_bfloat16>(g_Wbi_bf);
    __nv_bfloat16* p_aff_bf   = sym_addr<__nv_bfloat16>(g_aff_bf);

    cudaFuncSetAttribute(gemm_mma<0>, cudaFuncAttributeMaxDynamicSharedMemorySize, SMEM_BYTES);
    cudaFuncSetAttribute(gemm_mma<1>, cudaFuncAttributeMaxDynamicSharedMemorySize, SMEM_BYTES);
    cudaFuncSetAttribute(gemm_mma<2>, cudaFuncAttributeMaxDynamicSharedMemorySize, SMEM_BYTES);
    cudaFuncSetAttribute(gemm_mma<3>, cudaFuncAttributeMaxDynamicSharedMemorySize, SMEM_BYTES);

    // 0. zero split-buffer padding lanes (graph-replay determinism)
    {
        long tot = (long)M_ * 48 + 2l * M_ * 42 + (long)B_ * 800 * 42;
        zero_pads<<<(int)((tot + 255) / 256), 256>>>();
    }

    // 1. weight prep + conversions (one-time-ish, tiny)
    prep_kernel<<<(PROJN * REDUC + 255) / 256, 256>>>(
        W_ap, b_ap, W_op, b_op, W_ap2, b_ap2, W_op2, b_op2, W_bi);
    conv_split<<<REDUC, 128>>>(W_reduc, FEAT, 0, p_Wr_bf, KP_H, FEAT);
    conv_split<<<PROJN, 128>>>(p_WprojF, REDUC, 0, p_Wp_bf, KP_R, REDUC);
    conv_split<<<PROJN, 128>>>(W_bi, 151, 0, p_Wbi_bf, KP_N, HID);

    // 2. pool + embed -> split-bf16 h
    pool_embed_bf<<<M_, 256>>>(bert, positions, postag, embed);

    // 3. reduc = h @ W_reduc^T + b -> split-bf16 directly  [25600,400], T=13
    gemm_mma<1><<<dim3((REDUC + 127) / 128, M_ / 128, 1), 256, SMEM_BYTES>>>(
        p_hbf, 2 * KP_H, 0, M_, p_Wr_bf, 2 * KP_H, 0, REDUC,
        b_reduc, nullptr, 0, 0, p_reduc_bf, nullptr, KP_R, KP_H / 64, 0);

    // 4. fused projections + relu: fp32 proj (cols<300) + split apn/opn  T=7
    gemm_mma<2><<<dim3((PROJN + 127) / 128, M_ / 128, 1), 256, SMEM_BYTES>>>(
        p_reduc_bf, 2 * KP_R, 0, M_, p_Wp_bf, 2 * KP_R, 0, PROJN,
        p_bproj, p_proj, PROJN, 0, p_apn_bf, p_opn_bf, KP_N, KP_R / 64, 1);

    // 5. affine = ap_node @ W_bi[:, :150]^T + bbi -> split-bf16 [102400,150]  T=3
    gemm_mma<3><<<dim3((PROJN + 127) / 128, M_ / 128, 1), 256, SMEM_BYTES>>>(
        p_apn_bf, 2 * KP_N, 0, M_, p_Wbi_bf, 2 * KP_N, 0, PROJN,
        p_bbi, nullptr, 0, 0, p_aff_bf, nullptr, KP_N, KP_N / 64, 0);

    // 6. tag heads -> out[0 : 256000]
    tag_kernel<<<(M_ * 10 + 255) / 256, 256>>>(W_aptag, b_aptag, W_optag, b_optag, out);

    // 7. triplet per batch: C[l2, l1*4+p] = op_node[l2,:] . affine[l1*4+p,:]
    gemm_mma<0><<<dim3((800 + 127) / 128, (L_ + 127) / 128, B_), 256, SMEM_BYTES>>>(
        p_opn_bf, 2 * KP_N, (long)L_ * 2 * KP_N, L_,
        p_aff_bf, 2 * KP_N, (long)800 * 2 * KP_N, 800,
        nullptr, out + 2l * M_ * TAGS, 800, 160000l,
        nullptr, nullptr, 0, KP_N / 64, 0);
}

// round 8
// speedup vs baseline: 1.0700x; 1.0700x over previous
#include <cuda_runtime.h>
#include <cuda_bf16.h>
#include <cstdint>

// ---------------------------------------------------------------------------
// Problem constants
// ---------------------------------------------------------------------------
#define B_    128
#define S_    256
#define L_    200
#define D_    768
#define POSD  50
#define FEAT  818
#define REDUC 400
#define HID   150
#define PROJN 600
#define TAGS  5
#define POL   4
#define M_    25600

// K paddings (chunks of 64 bf16); buffers hold [hi(Kp) | lo(Kp)] per row
#define KP_H   832   // FEAT=818 -> T=13
#define KP_R   448   // REDUC=400 -> T=7
#define KP_N   192   // HID=150 -> T=3

// ---------------------------------------------------------------------------
// Scratch
// ---------------------------------------------------------------------------
__device__ __align__(128) __nv_bfloat16 g_hbf[(long)M_ * 2 * KP_H];
__device__ __align__(128) __nv_bfloat16 g_Wr_bf[(long)REDUC * 2 * KP_H];
__device__ float g_reduc[(long)M_ * REDUC];
__device__ __align__(128) __nv_bfloat16 g_reduc_bf[(long)M_ * 2 * KP_R];
__device__ float g_WprojF[PROJN * REDUC];
__device__ __align__(128) __nv_bfloat16 g_Wp_bf[(long)PROJN * 2 * KP_R];
__device__ float g_bproj[PROJN];
__device__ float g_bbi[PROJN];
__device__ float g_proj[(long)M_ * PROJN];
__device__ __align__(128) __nv_bfloat16 g_apn_bf[(long)M_ * 2 * KP_N];
__device__ __align__(128) __nv_bfloat16 g_opn_bf[(long)M_ * 2 * KP_N];
__device__ __align__(128) __nv_bfloat16 g_Wbi_bf[(long)PROJN * 2 * KP_N];
__device__ float g_affine[(long)M_ * PROJN];
__device__ __align__(128) __nv_bfloat16 g_aff_bf[(long)B_ * 800 * 2 * KP_N];

// ---------------------------------------------------------------------------
// PTX helpers (family-common only: cp.async / ldmatrix / mma.sync)
// ---------------------------------------------------------------------------
__device__ __forceinline__ uint32_t smem_u32(const void* p) {
    uint32_t a;
    asm("{ .reg .u64 t; cvta.to.shared.u64 t, %1; cvt.u32.u64 %0, t; }" : "=r"(a) : "l"(p));
    return a;
}
__device__ __forceinline__ void cp_async16(uint32_t dst, const void* src, int sz) {
    asm volatile("cp.async.cg.shared.global [%0], [%1], 16, %2;"
                 :: "r"(dst), "l"(src), "r"(sz) : "memory");
}
#define CP_COMMIT() asm volatile("cp.async.commit_group;" ::: "memory")
#define CP_WAIT(n)  asm volatile("cp.async.wait_group %0;" :: "n"(n) : "memory")

__device__ __forceinline__ uint32_t swz(uint32_t off) {
    return off ^ ((off >> 3) & 0x70);
}
__device__ __forceinline__ void ldsm_x4(uint32_t* r, uint32_t addr) {
    asm volatile("ldmatrix.sync.aligned.m8n8.x4.shared.b16 {%0,%1,%2,%3}, [%4];"
                 : "=r"(r[0]), "=r"(r[1]), "=r"(r[2]), "=r"(r[3]) : "r"(addr));
}
__device__ __forceinline__ void ldsm_x2(uint32_t* r, uint32_t addr) {
    asm volatile("ldmatrix.sync.aligned.m8n8.x2.shared.b16 {%0,%1}, [%2];"
                 : "=r"(r[0]), "=r"(r[1]) : "r"(addr));
}
__device__ __forceinline__ void mma_bf16(float* c, const uint32_t* a, const uint32_t* b) {
    asm volatile(
        "mma.sync.aligned.m16n8k16.row.col.f32.bf16.bf16.f32 "
        "{%0,%1,%2,%3}, {%4,%5,%6,%7}, {%8,%9}, {%0,%1,%2,%3};"
        : "+f"(c[0]), "+f"(c[1]), "+f"(c[2]), "+f"(c[3])
        : "r"(a[0]), "r"(a[1]), "r"(a[2]), "r"(a[3]), "r"(b[0]), "r"(b[1]));
}

// ---------------------------------------------------------------------------
// mma.sync split-bf16 GEMM, CTA 128x128, BK=64.
// 3-stage cp.async pipeline, ONE __syncthreads per chunk, loads 2 chunks ahead.
// Coalesced fp32 epilogue (R6-proven).
// ---------------------------------------------------------------------------
#define SMEM_BYTES 98304   // 3 stages x (16KB A + 16KB B)

__global__ __launch_bounds__(256, 2)
void gemm_mma(const __nv_bfloat16* __restrict__ A, int lda, long sA, int Mrows,
              const __nv_bfloat16* __restrict__ Bw, int ldb, long sB, int Nrows,
              const float* __restrict__ bias,
              float* __restrict__ C, int ldc, long sC,
              int T, int relu)
{
    extern __shared__ char smem[];
    const uint32_t sbase = smem_u32(smem);
    const int tid = threadIdx.x, wid = tid >> 5, lane = tid & 31;
    const int m0 = blockIdx.y * 128;
    const int n0 = blockIdx.x * 128;
    A  += (long)blockIdx.z * sA;
    Bw += (long)blockIdx.z * sB;
    C  += (long)blockIdx.z * sC;
    const int NT = 3 * T;

    const int wm = wid & 1;        // 0..1 : M quadrant (64 rows)
    const int wn = wid >> 1;       // 0..3 : N quadrant (32 cols)

    float acc[4][4][4];
#pragma unroll
    for (int i = 0; i < 4; i++)
#pragma unroll
        for (int j = 0; j < 4; j++)
#pragma unroll
            for (int k = 0; k < 4; k++) acc[i][j][k] = 0.0f;

    auto load_stage = [&](int t, int buf) {
        const int ka = (t < T) ? t : t - T;            // A: hi, hi, lo
        const int kb = (t < 2 * T) ? t : t - 2 * T;    // B: hi, lo, hi
        const uint32_t abase = sbase + (uint32_t)buf * 32768u;
        const uint32_t bbase = abase + 16384u;
#pragma unroll
        for (int i = 0; i < 4; i++) {
            int idx = i * 256 + tid;            // 0..1023
            int r = idx >> 3, c = idx & 7;
            int gm = m0 + r;
            int ok = (gm < Mrows);
            const char* src = (const char*)(A + (long)(ok ? gm : 0) * lda + (long)ka * 64) + c * 16;
            cp_async16(abase + swz((uint32_t)(r * 128 + c * 16)), src, ok ? 16 : 0);
        }
#pragma unroll
        for (int i = 0; i < 4; i++) {
            int idx = i * 256 + tid;
            int r = idx >> 3, c = idx & 7;
            int gn = n0 + r;
            int ok = (gn < Nrows);
            const char* src = (const char*)(Bw + (long)(ok ? gn : 0) * ldb + (long)kb * 64) + c * 16;
            cp_async16(bbase + swz((uint32_t)(r * 128 + c * 16)), src, ok ? 16 : 0);
        }
        CP_COMMIT();
    };

    load_stage(0, 0);
    if (NT > 1) load_stage(1, 1);

    int buf = 0;
    for (int t = 0; t < NT; t++) {
        if (t + 1 < NT) { CP_WAIT(1); } else { CP_WAIT(0); }
        __syncthreads();
        if (t + 2 < NT) {
            int nb = buf + 2; if (nb >= 3) nb -= 3;
            load_stage(t + 2, nb);   // overwrites buffer of chunk t-1 (safe: sync above)
        }
        const uint32_t abase = sbase + (uint32_t)buf * 32768u;
        const uint32_t bbase = abase + 16384u;
#pragma unroll
        for (int ks = 0; ks < 4; ks++) {
            uint32_t ra[4][4], rb[4][2];
#pragma unroll
            for (int mi = 0; mi < 4; mi++) {
                int row = wm * 64 + mi * 16 + (lane & 15);
                uint32_t off = (uint32_t)(row * 128 + ks * 32 + (lane >> 4) * 16);
                ldsm_x4(ra[mi], abase + swz(off));
            }
#pragma unroll
            for (int ni = 0; ni < 4; ni++) {
                int l16 = lane & 15;
                int row = wn * 32 + ni * 8 + (l16 & 7);
                uint32_t off = (uint32_t)(row * 128 + ks * 32 + ((l16 >> 3) & 1) * 16);
                ldsm_x2(rb[ni], bbase + swz(off));
            }
#pragma unroll
            for (int mi = 0; mi < 4; mi++)
#pragma unroll
                for (int ni = 0; ni < 4; ni++)
                    mma_bf16(acc[mi][ni], ra[mi], rb[ni]);
        }
        buf++; if (buf >= 3) buf = 0;
    }

    // epilogue: fragment layout c0:(r,c) c1:(r,c+1) c2:(r+8,c) c3:(r+8,c+1)
#pragma unroll
    for (int mi = 0; mi < 4; mi++) {
        int rb0 = m0 + wm * 64 + mi * 16 + (lane >> 2);
#pragma unroll
        for (int ni = 0; ni < 4; ni++) {
            int cb = n0 + wn * 32 + ni * 8 + (lane & 3) * 2;
#pragma unroll
            for (int half = 0; half < 2; half++) {
                int gm = rb0 + half * 8;
                if (gm >= Mrows) continue;
                float* crow = C + (long)gm * ldc;
#pragma unroll
                for (int e = 0; e < 2; e++) {
                    int gn = cb + e;
                    if (gn >= Nrows) continue;
                    float v = acc[mi][ni][half * 2 + e];
                    if (bias) v += bias[gn];
                    if (relu) v = fmaxf(v, 0.0f);
                    crow[gn] = v;
                }
            }
        }
    }
}

// ---------------------------------------------------------------------------
// Prep: concat projection weights (fp32), biases, biaffine bias column
// ---------------------------------------------------------------------------
__global__ void prep_kernel(const float* __restrict__ Wap, const float* __restrict__ bap,
                            const float* __restrict__ Wop, const float* __restrict__ bop,
                            const float* __restrict__ Wap2, const float* __restrict__ bap2,
                            const float* __restrict__ Wop2, const float* __restrict__ bop2,
                            const float* __restrict__ Wbi)
{
    int i = blockIdx.x * blockDim.x + threadIdx.x;
    if (i < PROJN * REDUC) {
        int n = i / REDUC, k = i % REDUC;
        const float* src = (n < 150) ? Wap : (n < 300) ? Wop : (n < 450) ? Wap2 : Wop2;
        g_WprojF[i] = src[(n % 150) * REDUC + k];
    }
    if (i < PROJN) {
        const float* sb = (i < 150) ? bap : (i < 300) ? bop : (i < 450) ? bap2 : bop2;
        g_bproj[i] = sb[i % 150];
        g_bbi[i]   = Wbi[i * 151 + 150];
    }
}

// ---------------------------------------------------------------------------
// Split fp32 -> [hi|lo] bf16 rows (grid.x = row); coalesced both directions
// ---------------------------------------------------------------------------
__global__ void conv_split(const float* __restrict__ src, int sld, int soff,
                           __nv_bfloat16* __restrict__ dst, int Kp, int K)
{
    long r = blockIdx.x;
    const float* s = src + r * (long)sld + soff;
    __nv_bfloat16* d = dst + r * (long)(2 * Kp);
    for (int k = threadIdx.x; k < Kp; k += blockDim.x) {
        float v = (k < K) ? s[k] : 0.0f;
        __nv_bfloat16 hi = __float2bfloat16(v);
        float lo = v - __bfloat162float(hi);
        d[k]      = hi;
        d[Kp + k] = __float2bfloat16(lo);
    }
}

// ---------------------------------------------------------------------------
// Pool subwords + POS embed, writing split-bf16 h directly [m, 2*KP_H]
// ---------------------------------------------------------------------------
__global__ void pool_embed_bf(const float* __restrict__ bert,
                              const int* __restrict__ positions,
                              const int* __restrict__ postag,
                              const float* __restrict__ embed)
{
    int m = blockIdx.x;
    int b = m / L_;
    __shared__ int s_start, s_end, s_tag;
    if (threadIdx.x == 0) {
        s_start = positions[m * 2 + 0];
        s_end   = positions[m * 2 + 1];
        s_tag   = postag[m];
    }
    __syncthreads();
    const int start = s_start, end = s_end, tag = s_tag;
    const float inv = 1.0f / (float)(end - start + 1);
    const float* bb = bert + (long)b * S_ * D_;
    __nv_bfloat16* hrow = g_hbf + (long)m * 2 * KP_H;
    for (int f = threadIdx.x; f < KP_H; f += blockDim.x) {
        float v = 0.0f;
        if (f < POSD) {
            v = embed[tag * POSD + f];
        } else if (f < FEAT) {
            int d = f - POSD;
            float s = 0.0f;
            for (int si = start; si <= end; si++) s += bb[(long)si * D_ + d];
            v = s * inv;
        }
        __nv_bfloat16 hi = __float2bfloat16(v);
        float lo = v - __bfloat162float(hi);
        hrow[f]        = hi;
        hrow[KP_H + f] = __float2bfloat16(lo);
    }
}

// ---------------------------------------------------------------------------
// Tag heads (fp32, tiny)
// ---------------------------------------------------------------------------
__global__ void tag_kernel(const float* __restrict__ Wap, const float* __restrict__ bap,
                           const float* __restrict__ Wop, const float* __restrict__ bop,
                           float* __restrict__ out)
{
    int i = blockIdx.x * blockDim.x + threadIdx.x;
    if (i >= M_ * 2 * TAGS) return;
    int m = i / (2 * TAGS);
    int r = i % (2 * TAGS);
    int t = r % TAGS;
    bool is_op = (r >= TAGS);
    const float* a = g_proj + (long)m * PROJN + (is_op ? 150 : 0);
    const float* w = (is_op ? Wop : Wap) + t * HID;
    float s = (is_op ? bop : bap)[t];
#pragma unroll 5
    for (int k = 0; k < HID; k++) s += a[k] * w[k];
    out[(is_op ? (long)M_ * TAGS : 0l) + (long)m * TAGS + t] = s;
}

// ---------------------------------------------------------------------------
// kernel_launch
// ---------------------------------------------------------------------------
template <typename T_>
static T_* sym_addr(const void* symbol) {
    void* p = nullptr;
    cudaGetSymbolAddress(&p, symbol);
    return (T_*)p;
}

extern "C" void kernel_launch(void* const* d_in, const int* in_sizes, int n_in,
                              void* d_out, int out_size)
{
    const float* bert      = (const float*)d_in[0];
    const int*   positions = (const int*)  d_in[1];
    const int*   postag    = (const int*)  d_in[2];
    const float* embed     = (const float*)d_in[3];
    const float* W_reduc   = (const float*)d_in[4];
    const float* b_reduc   = (const float*)d_in[5];
    const float* W_ap      = (const float*)d_in[6];
    const float* b_ap      = (const float*)d_in[7];
    const float* W_op      = (const float*)d_in[8];
    const float* b_op      = (const float*)d_in[9];
    const float* W_ap2     = (const float*)d_in[10];
    const float* b_ap2     = (const float*)d_in[11];
    const float* W_op2     = (const float*)d_in[12];
    const float* b_op2     = (const float*)d_in[13];
    const float* W_aptag   = (const float*)d_in[14];
    const float* b_aptag   = (const float*)d_in[15];
    const float* W_optag   = (const float*)d_in[16];
    const float* b_optag   = (const float*)d_in[17];
    const float* W_bi      = (const float*)d_in[18];
    float* out = (float*)d_out;

    __nv_bfloat16* p_hbf      = sym_addr<__nv_bfloat16>(g_hbf);
    __nv_bfloat16* p_Wr_bf    = sym_addr<__nv_bfloat16>(g_Wr_bf);
    float*         p_reduc    = sym_addr<float>(g_reduc);
    __nv_bfloat16* p_reduc_bf = sym_addr<__nv_bfloat16>(g_reduc_bf);
    float*         p_WprojF   = sym_addr<float>(g_WprojF);
    __nv_bfloat16* p_Wp_bf    = sym_addr<__nv_bfloat16>(g_Wp_bf);
    float*         p_bproj    = sym_addr<float>(g_bproj);
    float*         p_bbi      = sym_addr<float>(g_bbi);
    float*         p_proj     = sym_addr<float>(g_proj);
    __nv_bfloat16* p_apn_bf   = sym_addr<__nv_bfloat16>(g_apn_bf);
    __nv_bfloat16* p_opn_bf   = sym_addr<__nv_bfloat16>(g_opn_bf);
    __nv_bfloat16* p_Wbi_bf   = sym_addr<__nv_bfloat16>(g_Wbi_bf);
    float*         p_affine   = sym_addr<float>(g_affine);
    __nv_bfloat16* p_aff_bf   = sym_addr<__nv_bfloat16>(g_aff_bf);

    cudaFuncSetAttribute(gemm_mma, cudaFuncAttributeMaxDynamicSharedMemorySize, SMEM_BYTES);

    // 1. weight prep + conversions
    prep_kernel<<<(PROJN * REDUC + 255) / 256, 256>>>(
        W_ap, b_ap, W_op, b_op, W_ap2, b_ap2, W_op2, b_op2, W_bi);
    conv_split<<<REDUC, 128>>>(W_reduc, FEAT, 0, p_Wr_bf, KP_H, FEAT);
    conv_split<<<PROJN, 128>>>(p_WprojF, REDUC, 0, p_Wp_bf, KP_R, REDUC);
    conv_split<<<PROJN, 128>>>(W_bi, 151, 0, p_Wbi_bf, KP_N, HID);

    // 2. pool + embed -> split-bf16 h
    pool_embed_bf<<<M_, 256>>>(bert, positions, postag, embed);

    // 3. reduc = h @ W_reduc^T + b    [25600, 400], T=13
    gemm_mma<<<dim3((REDUC + 127) / 128, M_ / 128, 1), 256, SMEM_BYTES>>>(
        p_hbf, 2 * KP_H, 0, M_, p_Wr_bf, 2 * KP_H, 0, REDUC,
        b_reduc, p_reduc, REDUC, 0, KP_H / 64, 0);
    conv_split<<<M_, 128>>>(p_reduc, REDUC, 0, p_reduc_bf, KP_R, REDUC);

    // 4. fused projections + relu -> proj [25600, 600], T=7
    gemm_mma<<<dim3((PROJN + 127) / 128, M_ / 128, 1), 256, SMEM_BYTES>>>(
        p_reduc_bf, 2 * KP_R, 0, M_, p_Wp_bf, 2 * KP_R, 0, PROJN,
        p_bproj, p_proj, PROJN, 0, KP_R / 64, 1);
    conv_split<<<M_, 128>>>(p_proj, PROJN, 300, p_apn_bf, KP_N, HID);
    conv_split<<<M_, 128>>>(p_proj, PROJN, 450, p_opn_bf, KP_N, HID);

    // 5. affine = ap_node @ W_bi[:, :150]^T + bbi  [25600, 600], T=3
    gemm_mma<<<dim3((PROJN + 127) / 128, M_ / 128, 1), 256, SMEM_BYTES>>>(
        p_apn_bf, 2 * KP_N, 0, M_, p_Wbi_bf, 2 * KP_N, 0, PROJN,
        p_bbi, p_affine, PROJN, 0, KP_N / 64, 0);
    // affine fp32 [25600,600] flat == [102400,150] rows -> split-bf16
    conv_split<<<B_ * 800, 128>>>(p_affine, HID, 0, p_aff_bf, KP_N, HID);

    // 6. tag heads -> out[0 : 256000]
    tag_kernel<<<(M_ * 10 + 255) / 256, 256>>>(W_aptag, b_aptag, W_optag, b_optag, out);

    // 7. triplet per batch: C[l2, l1*4+p] = op_node[l2,:] . affine[l1*4+p,:]
    gemm_mma<<<dim3((800 + 127) / 128, (L_ + 127) / 128, B_), 256, SMEM_BYTES>>>(
        p_opn_bf, 2 * KP_N, (long)L_ * 2 * KP_N, L_,
        p_aff_bf, 2 * KP_N, (long)800 * 2 * KP_N, 800,
        nullptr, out + 2l * M_ * TAGS, 800, 160000l,
        KP_N / 64, 0);
}

// round 9
// speedup vs baseline: 1.1354x; 1.0611x over previous
#include <cuda_runtime.h>
#include <cuda_bf16.h>
#include <cstdint>

// ---------------------------------------------------------------------------
// Problem constants
// ---------------------------------------------------------------------------
#define B_    128
#define S_    256
#define L_    200
#define D_    768
#define POSD  50
#define FEAT  818
#define REDUC 400
#define HID   150
#define PROJN 600
#define TAGS  5
#define POL   4
#define M_    25600

// Concatenated-K totals: 3*K rounded up to 64
#define KT_H  2496   // 3*818=2454 -> 39 chunks
#define KT_R  1216   // 3*400=1200 -> 19 chunks
#define KT_N  512    // 3*150=450  -> 8 chunks

// ---------------------------------------------------------------------------
// Scratch
// ---------------------------------------------------------------------------
__device__ __align__(128) __nv_bfloat16 g_hbf[(long)M_ * KT_H];       // A-layout [hi|hi|lo]
__device__ __align__(128) __nv_bfloat16 g_Wr_bf[(long)REDUC * KT_H];  // B-layout [hi|lo|hi]
__device__ float g_reduc[(long)M_ * REDUC];
__device__ __align__(128) __nv_bfloat16 g_reduc_bf[(long)M_ * KT_R];  // A-layout
__device__ float g_WprojF[PROJN * REDUC];
__device__ __align__(128) __nv_bfloat16 g_Wp_bf[(long)PROJN * KT_R];  // B-layout
__device__ float g_bproj[PROJN];
__device__ float g_bbi[PROJN];
__device__ float g_proj[(long)M_ * PROJN];
__device__ __align__(128) __nv_bfloat16 g_apn_bf[(long)M_ * KT_N];    // A-layout
__device__ __align__(128) __nv_bfloat16 g_opn_bf[(long)M_ * KT_N];    // A-layout
__device__ __align__(128) __nv_bfloat16 g_Wbi_bf[(long)PROJN * KT_N]; // B-layout
__device__ float g_affine[(long)M_ * PROJN];
__device__ __align__(128) __nv_bfloat16 g_aff_bf[(long)B_ * 800 * KT_N]; // B-layout

// ---------------------------------------------------------------------------
// PTX helpers (family-common only: cp.async / ldmatrix / mma.sync)
// ---------------------------------------------------------------------------
__device__ __forceinline__ uint32_t smem_u32(const void* p) {
    uint32_t a;
    asm("{ .reg .u64 t; cvta.to.shared.u64 t, %1; cvt.u32.u64 %0, t; }" : "=r"(a) : "l"(p));
    return a;
}
__device__ __forceinline__ void cp_async16(uint32_t dst, const void* src, int sz) {
    asm volatile("cp.async.cg.shared.global [%0], [%1], 16, %2;"
                 :: "r"(dst), "l"(src), "r"(sz) : "memory");
}
#define CP_COMMIT() asm volatile("cp.async.commit_group;" ::: "memory")
#define CP_WAIT(n)  asm volatile("cp.async.wait_group %0;" :: "n"(n) : "memory")

__device__ __forceinline__ uint32_t swz(uint32_t off) {
    return off ^ ((off >> 3) & 0x70);
}
__device__ __forceinline__ void ldsm_x4(uint32_t* r, uint32_t addr) {
    asm volatile("ldmatrix.sync.aligned.m8n8.x4.shared.b16 {%0,%1,%2,%3}, [%4];"
                 : "=r"(r[0]), "=r"(r[1]), "=r"(r[2]), "=r"(r[3]) : "r"(addr));
}
__device__ __forceinline__ void ldsm_x2(uint32_t* r, uint32_t addr) {
    asm volatile("ldmatrix.sync.aligned.m8n8.x2.shared.b16 {%0,%1}, [%2];"
                 : "=r"(r[0]), "=r"(r[1]) : "r"(addr));
}
__device__ __forceinline__ void mma_bf16(float* c, const uint32_t* a, const uint32_t* b) {
    asm volatile(
        "mma.sync.aligned.m16n8k16.row.col.f32.bf16.bf16.f32 "
        "{%0,%1,%2,%3}, {%4,%5,%6,%7}, {%8,%9}, {%0,%1,%2,%3};"
        : "+f"(c[0]), "+f"(c[1]), "+f"(c[2]), "+f"(c[3])
        : "r"(a[0]), "r"(a[1]), "r"(a[2]), "r"(a[3]), "r"(b[0]), "r"(b[1]));
}

// ---------------------------------------------------------------------------
// mma.sync GEMM over concatenated-K layout.  CTA tile 128 x BN, BK=64,
// 2-stage cp.async double buffer (R6-proven loop).
//   BN=128: 8 warps as 2(M)x4(N), warp tile 64x32
//   BN=64 : 8 warps as 4(M)x2(N), warp tile 32x32
// ---------------------------------------------------------------------------
template<int BN>
__global__ __launch_bounds__(256, 2)
void gemm_mma(const __nv_bfloat16* __restrict__ A, int lda, long sA, int Mrows,
              const __nv_bfloat16* __restrict__ Bw, int ldb, long sB, int Nrows,
              const float* __restrict__ bias,
              float* __restrict__ C, int ldc, long sC,
              int NT, int n0base, int relu)
{
    constexpr int WN = BN / 32;       // warps along N
    constexpr int WM = 8 / WN;        // warps along M
    constexpr int MI = 128 / (WM * 16);
    constexpr int NI = 4;
    constexpr uint32_t ABYTES = 16384u;
    constexpr uint32_t BBYTES = (uint32_t)BN * 128u;
    constexpr uint32_t STAGE  = ABYTES + BBYTES;

    extern __shared__ char smem[];
    const uint32_t sbase = smem_u32(smem);
    const int tid = threadIdx.x, wid = tid >> 5, lane = tid & 31;
    const int m0 = blockIdx.y * 128;
    const int n0 = n0base + blockIdx.x * BN;
    A  += (long)blockIdx.z * sA;
    Bw += (long)blockIdx.z * sB;
    C  += (long)blockIdx.z * sC;

    const int wm = wid % WM;
    const int wn = wid / WM;

    float acc[MI][NI][4];
#pragma unroll
    for (int i = 0; i < MI; i++)
#pragma unroll
        for (int j = 0; j < NI; j++)
#pragma unroll
            for (int k = 0; k < 4; k++) acc[i][j][k] = 0.0f;

    auto load_stage = [&](int t, int buf) {
        const uint32_t abase = sbase + (uint32_t)buf * STAGE;
        const uint32_t bbase = abase + ABYTES;
#pragma unroll
        for (int i = 0; i < 4; i++) {
            int idx = i * 256 + tid;            // 0..1023
            int r = idx >> 3, c = idx & 7;
            int gm = m0 + r;
            int ok = (gm < Mrows);
            const char* src = (const char*)(A + (long)(ok ? gm : 0) * lda + (long)t * 64) + c * 16;
            cp_async16(abase + swz((uint32_t)(r * 128 + c * 16)), src, ok ? 16 : 0);
        }
#pragma unroll
        for (int i = 0; i < BN / 32; i++) {
            int idx = i * 256 + tid;
            int r = idx >> 3, c = idx & 7;
            int gn = n0 + r;
            int ok = (gn < Nrows);
            const char* src = (const char*)(Bw + (long)(ok ? gn : 0) * ldb + (long)t * 64) + c * 16;
            cp_async16(bbase + swz((uint32_t)(r * 128 + c * 16)), src, ok ? 16 : 0);
        }
        CP_COMMIT();
    };

    load_stage(0, 0);

    for (int t = 0; t < NT; t++) {
        const int buf = t & 1;
        if (t + 1 < NT) {
            load_stage(t + 1, buf ^ 1);
            CP_WAIT(1);
        } else {
            CP_WAIT(0);
        }
        __syncthreads();

        const uint32_t abase = sbase + (uint32_t)buf * STAGE;
        const uint32_t bbase = abase + ABYTES;
#pragma unroll
        for (int ks = 0; ks < 4; ks++) {
            uint32_t ra[MI][4], rb[NI][2];
#pragma unroll
            for (int mi = 0; mi < MI; mi++) {
                int row = wm * (MI * 16) + mi * 16 + (lane & 15);
                uint32_t off = (uint32_t)(row * 128 + ks * 32 + (lane >> 4) * 16);
                ldsm_x4(ra[mi], abase + swz(off));
            }
#pragma unroll
            for (int ni = 0; ni < NI; ni++) {
                int l16 = lane & 15;
                int row = wn * 32 + ni * 8 + (l16 & 7);
                uint32_t off = (uint32_t)(row * 128 + ks * 32 + ((l16 >> 3) & 1) * 16);
                ldsm_x2(rb[ni], bbase + swz(off));
            }
#pragma unroll
            for (int mi = 0; mi < MI; mi++)
#pragma unroll
                for (int ni = 0; ni < NI; ni++)
                    mma_bf16(acc[mi][ni], ra[mi], rb[ni]);
        }
        __syncthreads();
    }

    // epilogue: fragment layout c0:(r,c) c1:(r,c+1) c2:(r+8,c) c3:(r+8,c+1)
#pragma unroll
    for (int mi = 0; mi < MI; mi++) {
        int rb0 = m0 + wm * (MI * 16) + mi * 16 + (lane >> 2);
#pragma unroll
        for (int ni = 0; ni < NI; ni++) {
            int cb = n0 + wn * 32 + ni * 8 + (lane & 3) * 2;
#pragma unroll
            for (int half = 0; half < 2; half++) {
                int gm = rb0 + half * 8;
                if (gm >= Mrows) continue;
                float* crow = C + (long)gm * ldc;
#pragma unroll
                for (int e = 0; e < 2; e++) {
                    int gn = cb + e;
                    if (gn >= Nrows) continue;
                    float v = acc[mi][ni][half * 2 + e];
                    if (bias) v += bias[gn];
                    if (relu) v = fmaxf(v, 0.0f);
                    crow[gn] = v;
                }
            }
        }
    }
}

// ---------------------------------------------------------------------------
// Prep: concat projection weights (fp32), biases, biaffine bias column
// ---------------------------------------------------------------------------
__global__ void prep_kernel(const float* __restrict__ Wap, const float* __restrict__ bap,
                            const float* __restrict__ Wop, const float* __restrict__ bop,
                            const float* __restrict__ Wap2, const float* __restrict__ bap2,
                            const float* __restrict__ Wop2, const float* __restrict__ bop2,
                            const float* __restrict__ Wbi)
{
    int i = blockIdx.x * blockDim.x + threadIdx.x;
    if (i < PROJN * REDUC) {
        int n = i / REDUC, k = i % REDUC;
        const float* src = (n < 150) ? Wap : (n < 300) ? Wop : (n < 450) ? Wap2 : Wop2;
        g_WprojF[i] = src[(n % 150) * REDUC + k];
    }
    if (i < PROJN) {
        const float* sb = (i < 150) ? bap : (i < 300) ? bop : (i < 450) ? bap2 : bop2;
        g_bproj[i] = sb[i % 150];
        g_bbi[i]   = Wbi[i * 151 + 150];
    }
}

// ---------------------------------------------------------------------------
// fp32 -> concatenated split-bf16 rows.  grid.x = row.
// A-layout: [hi(K) | hi(K) | lo(K) | 0...]   (activations)
// B-layout: [hi(K) | lo(K) | hi(K) | 0...]   (weights / G4 B operand)
// ---------------------------------------------------------------------------
template<int ALAYOUT>
__global__ void conv_cat(const float* __restrict__ src, int sld, int soff,
                         __nv_bfloat16* __restrict__ dst, int KT, int K)
{
    long r = blockIdx.x;
    const float* s = src + r * (long)sld + soff;
    __nv_bfloat16* d = dst + r * (long)KT;
    for (int k = threadIdx.x; k < KT; k += blockDim.x) {
        float v = 0.0f;
        bool want_lo = false;
        if (k < K) {
            v = s[k];
        } else if (k < 2 * K) {
            v = s[k - K];
            if (!ALAYOUT) want_lo = true;      // B-layout: second region is lo
        } else if (k < 3 * K) {
            v = s[k - 2 * K];
            if (ALAYOUT) want_lo = true;       // A-layout: third region is lo
        }
        __nv_bfloat16 hi = __float2bfloat16(v);
        d[k] = want_lo ? __float2bfloat16(v - __bfloat162float(hi)) : hi;
    }
}

// ---------------------------------------------------------------------------
// Pool subwords + POS embed -> A-layout h [m, KT_H]
// ---------------------------------------------------------------------------
__global__ void pool_embed_bf(const float* __restrict__ bert,
                              const int* __restrict__ positions,
                              const int* __restrict__ postag,
                              const float* __restrict__ embed)
{
    int m = blockIdx.x;
    int b = m / L_;
    __shared__ int s_start, s_end, s_tag;
    if (threadIdx.x == 0) {
        s_start = positions[m * 2 + 0];
        s_end   = positions[m * 2 + 1];
        s_tag   = postag[m];
    }
    __syncthreads();
    const int start = s_start, end = s_end, tag = s_tag;
    const float inv = 1.0f / (float)(end - start + 1);
    const float* bb = bert + (long)b * S_ * D_;
    __nv_bfloat16* d = g_hbf + (long)m * KT_H;
    for (int f = threadIdx.x; f < FEAT; f += blockDim.x) {
        float v;
        if (f < POSD) {
            v = embed[tag * POSD + f];
        } else {
            int dd = f - POSD;
            float s = 0.0f;
            for (int si = start; si <= end; si++) s += bb[(long)si * D_ + dd];
            v = s * inv;
        }
        __nv_bfloat16 hi = __float2bfloat16(v);
        float lo = v - __bfloat162float(hi);
        d[f]            = hi;
        d[FEAT + f]     = hi;
        d[2 * FEAT + f] = __float2bfloat16(lo);
    }
    for (int f = 3 * FEAT + threadIdx.x; f < KT_H; f += blockDim.x)
        d[f] = __float2bfloat16(0.0f);
}

// ---------------------------------------------------------------------------
// Tag heads (fp32, tiny)
// ---------------------------------------------------------------------------
__global__ void tag_kernel(const float* __restrict__ Wap, const float* __restrict__ bap,
                           const float* __restrict__ Wop, const float* __restrict__ bop,
                           float* __restrict__ out)
{
    int i = blockIdx.x * blockDim.x + threadIdx.x;
    if (i >= M_ * 2 * TAGS) return;
    int m = i / (2 * TAGS);
    int r = i % (2 * TAGS);
    int t = r % TAGS;
    bool is_op = (r >= TAGS);
    const float* a = g_proj + (long)m * PROJN + (is_op ? 150 : 0);
    const float* w = (is_op ? Wop : Wap) + t * HID;
    float s = (is_op ? bop : bap)[t];
#pragma unroll 5
    for (int k = 0; k < HID; k++) s += a[k] * w[k];
    out[(is_op ? (long)M_ * TAGS : 0l) + (long)m * TAGS + t] = s;
}

// ---------------------------------------------------------------------------
// kernel_launch
// ---------------------------------------------------------------------------
template <typename T_>
static T_* sym_addr(const void* symbol) {
    void* p = nullptr;
    cudaGetSymbolAddress(&p, symbol);
    return (T_*)p;
}

#define SMEM128 (2 * (16384 + 128 * 128))
#define SMEM64  (2 * (16384 + 64 * 128))

extern "C" void kernel_launch(void* const* d_in, const int* in_sizes, int n_in,
                              void* d_out, int out_size)
{
    const float* bert      = (const float*)d_in[0];
    const int*   positions = (const int*)  d_in[1];
    const int*   postag    = (const int*)  d_in[2];
    const float* embed     = (const float*)d_in[3];
    const float* W_reduc   = (const float*)d_in[4];
    const float* b_reduc   = (const float*)d_in[5];
    const float* W_ap      = (const float*)d_in[6];
    const float* b_ap      = (const float*)d_in[7];
    const float* W_op      = (const float*)d_in[8];
    const float* b_op      = (const float*)d_in[9];
    const float* W_ap2     = (const float*)d_in[10];
    const float* b_ap2     = (const float*)d_in[11];
    const float* W_op2     = (const float*)d_in[12];
    const float* b_op2     = (const float*)d_in[13];
    const float* W_aptag   = (const float*)d_in[14];
    const float* b_aptag   = (const float*)d_in[15];
    const float* W_optag   = (const float*)d_in[16];
    const float* b_optag   = (const float*)d_in[17];
    const float* W_bi      = (const float*)d_in[18];
    float* out = (float*)d_out;

    __nv_bfloat16* p_hbf      = sym_addr<__nv_bfloat16>(g_hbf);
    __nv_bfloat16* p_Wr_bf    = sym_addr<__nv_bfloat16>(g_Wr_bf);
    float*         p_reduc    = sym_addr<float>(g_reduc);
    __nv_bfloat16* p_reduc_bf = sym_addr<__nv_bfloat16>(g_reduc_bf);
    float*         p_WprojF   = sym_addr<float>(g_WprojF);
    __nv_bfloat16* p_Wp_bf    = sym_addr<__nv_bfloat16>(g_Wp_bf);
    float*         p_bproj    = sym_addr<float>(g_bproj);
    float*         p_bbi      = sym_addr<float>(g_bbi);
    float*         p_proj     = sym_addr<float>(g_proj);
    __nv_bfloat16* p_apn_bf   = sym_addr<__nv_bfloat16>(g_apn_bf);
    __nv_bfloat16* p_opn_bf   = sym_addr<__nv_bfloat16>(g_opn_bf);
    __nv_bfloat16* p_Wbi_bf   = sym_addr<__nv_bfloat16>(g_Wbi_bf);
    float*         p_affine   = sym_addr<float>(g_affine);
    __nv_bfloat16* p_aff_bf   = sym_addr<__nv_bfloat16>(g_aff_bf);

    cudaFuncSetAttribute(gemm_mma<128>, cudaFuncAttributeMaxDynamicSharedMemorySize, SMEM128);
    cudaFuncSetAttribute(gemm_mma<64>,  cudaFuncAttributeMaxDynamicSharedMemorySize, SMEM64);

    // 1. weight prep + conversions (B-layout [hi|lo|hi])
    prep_kernel<<<(PROJN * REDUC + 255) / 256, 256>>>(
        W_ap, b_ap, W_op, b_op, W_ap2, b_ap2, W_op2, b_op2, W_bi);
    conv_cat<0><<<REDUC, 128>>>(W_reduc, FEAT, 0, p_Wr_bf, KT_H, FEAT);
    conv_cat<0><<<PROJN, 128>>>(p_WprojF, REDUC, 0, p_Wp_bf, KT_R, REDUC);
    conv_cat<0><<<PROJN, 128>>>(W_bi, 151, 0, p_Wbi_bf, KT_N, HID);

    // 2. pool + embed -> A-layout h [hi|hi|lo]
    pool_embed_bf<<<M_, 256>>>(bert, positions, postag, embed);

    // 3. reduc = h @ W_reduc^T + b    [25600, 400]  NT=39, tiles 3x128 + 1x64
    gemm_mma<128><<<dim3(3, M_ / 128, 1), 256, SMEM128>>>(
        p_hbf, KT_H, 0, M_, p_Wr_bf, KT_H, 0, REDUC,
        b_reduc, p_reduc, REDUC, 0, KT_H / 64, 0, 0);
    gemm_mma<64><<<dim3(1, M_ / 128, 1), 256, SMEM64>>>(
        p_hbf, KT_H, 0, M_, p_Wr_bf, KT_H, 0, REDUC,
        b_reduc, p_reduc, REDUC, 0, KT_H / 64, 384, 0);
    conv_cat<1><<<M_, 128>>>(p_reduc, REDUC, 0, p_reduc_bf, KT_R, REDUC);

    // 4. fused projections + relu -> proj [25600, 600]  NT=19
    gemm_mma<128><<<dim3(5, M_ / 128, 1), 256, SMEM128>>>(
        p_reduc_bf, KT_R, 0, M_, p_Wp_bf, KT_R, 0, PROJN,
        p_bproj, p_proj, PROJN, 0, KT_R / 64, 0, 1);
    conv_cat<1><<<M_, 128>>>(p_proj, PROJN, 300, p_apn_bf, KT_N, HID);
    conv_cat<1><<<M_, 128>>>(p_proj, PROJN, 450, p_opn_bf, KT_N, HID);

    // 5. affine = ap_node @ W_bi[:, :150]^T + bbi  [25600, 600]  NT=8
    gemm_mma<128><<<dim3(5, M_ / 128, 1), 256, SMEM128>>>(
        p_apn_bf, KT_N, 0, M_, p_Wbi_bf, KT_N, 0, PROJN,
        p_bbi, p_affine, PROJN, 0, KT_N / 64, 0, 0);
    // affine fp32 [25600,600] flat == [102400,150] rows -> B-layout split
    conv_cat<0><<<B_ * 800, 128>>>(p_affine, HID, 0, p_aff_bf, KT_N, HID);

    // 6. tag heads -> out[0 : 256000]
    tag_kernel<<<(M_ * 10 + 255) / 256, 256>>>(W_aptag, b_aptag, W_optag, b_optag, out);

    // 7. triplet per batch: C[l2, l1*4+p] = op_node[l2,:] . affine[l1*4+p,:]
    //    NT=8, tiles 6x128 + 1x64
    gemm_mma<128><<<dim3(6, (L_ + 127) / 128, B_), 256, SMEM128>>>(
        p_opn_bf, KT_N, (long)L_ * KT_N, L_,
        p_aff_bf, KT_N, (long)800 * KT_N, 800,
        nullptr, out + 2l * M_ * TAGS, 800, 160000l,
        KT_N / 64, 0, 0);
    gemm_mma<64><<<dim3(1, (L_ + 127) / 128, B_), 256, SMEM64>>>(
        p_opn_bf, KT_N, (long)L_ * KT_N, L_,
        p_aff_bf, KT_N, (long)800 * KT_N, 800,
        nullptr, out + 2l * M_ * TAGS, 800, 160000l,
        KT_N / 64, 768, 0);
}

// round 10
// speedup vs baseline: 1.3405x; 1.1807x over previous
#include <cuda_runtime.h>
#include <cuda_bf16.h>
#include <cstdint>

// ---------------------------------------------------------------------------
// Problem constants
// ---------------------------------------------------------------------------
#define B_    128
#define S_    256
#define L_    200
#define D_    768
#define POSD  50
#define FEAT  818
#define REDUC 400
#define HID   150
#define PROJN 600
#define TAGS  5
#define POL   4
#define M_    25600

// Concatenated-K totals: 3*K rounded up to 64
#define KT_H  2496   // 3*818=2454 -> 39 chunks
#define KT_R  1216   // 3*400=1200 -> 19 chunks
#define KT_N  512    // 3*150=450  -> 8 chunks

// ---------------------------------------------------------------------------
// Scratch  (pad lanes of split buffers are NEVER written -> stay zero forever)
// ---------------------------------------------------------------------------
__device__ __align__(128) __nv_bfloat16 g_hbf[(long)M_ * KT_H];       // A-layout [hi|hi|lo]
__device__ __align__(128) __nv_bfloat16 g_Wr_bf[(long)REDUC * KT_H];  // B-layout [hi|lo|hi]
__device__ __align__(128) __nv_bfloat16 g_reduc_bf[(long)M_ * KT_R];  // A-layout
__device__ float g_WprojF[PROJN * REDUC];
__device__ __align__(128) __nv_bfloat16 g_Wp_bf[(long)PROJN * KT_R];  // B-layout
__device__ float g_bproj[PROJN];
__device__ float g_bbi[PROJN];
__device__ float g_proj[(long)M_ * 300];                              // tag-head cols only
__device__ __align__(128) __nv_bfloat16 g_apn_bf[(long)M_ * KT_N];    // A-layout
__device__ __align__(128) __nv_bfloat16 g_opn_bf[(long)M_ * KT_N];    // A-layout
__device__ __align__(128) __nv_bfloat16 g_Wbi_bf[(long)PROJN * KT_N]; // B-layout
__device__ __align__(128) __nv_bfloat16 g_aff_bf[(long)B_ * 800 * KT_N]; // B-layout

// ---------------------------------------------------------------------------
// PTX helpers (family-common only: cp.async / ldmatrix / mma.sync)
// ---------------------------------------------------------------------------
__device__ __forceinline__ uint32_t smem_u32(const void* p) {
    uint32_t a;
    asm("{ .reg .u64 t; cvta.to.shared.u64 t, %1; cvt.u32.u64 %0, t; }" : "=r"(a) : "l"(p));
    return a;
}
__device__ __forceinline__ void cp_async16(uint32_t dst, const void* src, int sz) {
    asm volatile("cp.async.cg.shared.global [%0], [%1], 16, %2;"
                 :: "r"(dst), "l"(src), "r"(sz) : "memory");
}
#define CP_COMMIT() asm volatile("cp.async.commit_group;" ::: "memory")
#define CP_WAIT(n)  asm volatile("cp.async.wait_group %0;" :: "n"(n) : "memory")

__device__ __forceinline__ uint32_t swz(uint32_t off) {
    return off ^ ((off >> 3) & 0x70);
}
__device__ __forceinline__ void ldsm_x4(uint32_t* r, uint32_t addr) {
    asm volatile("ldmatrix.sync.aligned.m8n8.x4.shared.b16 {%0,%1,%2,%3}, [%4];"
                 : "=r"(r[0]), "=r"(r[1]), "=r"(r[2]), "=r"(r[3]) : "r"(addr));
}
__device__ __forceinline__ void ldsm_x2(uint32_t* r, uint32_t addr) {
    asm volatile("ldmatrix.sync.aligned.m8n8.x2.shared.b16 {%0,%1}, [%2];"
                 : "=r"(r[0]), "=r"(r[1]) : "r"(addr));
}
__device__ __forceinline__ void mma_bf16(float* c, const uint32_t* a, const uint32_t* b) {
    asm volatile(
        "mma.sync.aligned.m16n8k16.row.col.f32.bf16.bf16.f32 "
        "{%0,%1,%2,%3}, {%4,%5,%6,%7}, {%8,%9}, {%0,%1,%2,%3};"
        : "+f"(c[0]), "+f"(c[1]), "+f"(c[2]), "+f"(c[3])
        : "r"(a[0]), "r"(a[1]), "r"(a[2]), "r"(a[3]), "r"(b[0]), "r"(b[1]));
}
__device__ __forceinline__ uint32_t pack_hilo(float v) {
    __nv_bfloat16 hi = __float2bfloat16(v);
    __nv_bfloat16 lo = __float2bfloat16(v - __bfloat162float(hi));
    uint16_t hb = __nv_bfloat16_raw(hi).x;
    uint16_t lb = __nv_bfloat16_raw(lo).x;
    return (uint32_t)hb | ((uint32_t)lb << 16);
}
__device__ __forceinline__ __nv_bfloat16 bits_bf(uint16_t b) {
    __nv_bfloat16_raw r; r.x = b; return __nv_bfloat16(r);
}

// ---------------------------------------------------------------------------
// mma.sync GEMM over concatenated-K layout.  CTA tile 128 x BN, BK=64,
// 2-stage cp.async double buffer.
//   BN=128: 8 warps as 2(M)x4(N), warp tile 64x32
//   BN=64 : 8 warps as 4(M)x2(N), warp tile 32x32
// Epilogue (EPI):
//   0: direct fp32 store (triplet -> d_out)
//   1: smem-staged split-bf16 A-layout S0, K=400  (reduc)
//   2: staged: gn<300 fp32 Cf(ld 300); [300,450) S0 A-layout K=150; [450,600) S1
//   3: staged split-bf16 B-layout S0, row=gm*4+gn/150, k=gn%150  (affine)
// ---------------------------------------------------------------------------
template<int BN, int EPI>
__global__ __launch_bounds__(256, 2)
void gemm_mma(const __nv_bfloat16* __restrict__ A, int lda, long sA, int Mrows,
              const __nv_bfloat16* __restrict__ Bw, int ldb, long sB, int Nrows,
              const float* __restrict__ bias,
              float* __restrict__ Cf, int ldc, long sC,
              __nv_bfloat16* __restrict__ S0, __nv_bfloat16* __restrict__ S1,
              int NT, int n0base, int relu)
{
    constexpr int WN = BN / 32;       // warps along N
    constexpr int WM = 8 / WN;        // warps along M
    constexpr int MI = 128 / (WM * 16);
    constexpr int NI = 4;
    constexpr uint32_t ABYTES = 16384u;
    constexpr uint32_t BBYTES = (uint32_t)BN * 128u;
    constexpr uint32_t STAGEB = ABYTES + BBYTES;
    constexpr int SSTR = BN + 8;      // staging row stride (u32) -> ~2-way conflicts

    extern __shared__ char smem[];
    const uint32_t sbase = smem_u32(smem);
    const int tid = threadIdx.x, wid = tid >> 5, lane = tid & 31;
    const int m0 = blockIdx.y * 128;
    const int n0 = n0base + blockIdx.x * BN;
    A  += (long)blockIdx.z * sA;
    Bw += (long)blockIdx.z * sB;
    if (Cf) Cf += (long)blockIdx.z * sC;

    const int wm = wid % WM;
    const int wn = wid / WM;

    float acc[MI][NI][4];
#pragma unroll
    for (int i = 0; i < MI; i++)
#pragma unroll
        for (int j = 0; j < NI; j++)
#pragma unroll
            for (int k = 0; k < 4; k++) acc[i][j][k] = 0.0f;

    auto load_stage = [&](int t, int buf) {
        const uint32_t abase = sbase + (uint32_t)buf * STAGEB;
        const uint32_t bbase = abase + ABYTES;
#pragma unroll
        for (int i = 0; i < 4; i++) {
            int idx = i * 256 + tid;            // 0..1023
            int r = idx >> 3, c = idx & 7;
            int gm = m0 + r;
            int ok = (gm < Mrows);
            const char* src = (const char*)(A + (long)(ok ? gm : 0) * lda + (long)t * 64) + c * 16;
            cp_async16(abase + swz((uint32_t)(r * 128 + c * 16)), src, ok ? 16 : 0);
        }
#pragma unroll
        for (int i = 0; i < BN / 32; i++) {
            int idx = i * 256 + tid;
            int r = idx >> 3, c = idx & 7;
            int gn = n0 + r;
            int ok = (gn < Nrows);
            const char* src = (const char*)(Bw + (long)(ok ? gn : 0) * ldb + (long)t * 64) + c * 16;
            cp_async16(bbase + swz((uint32_t)(r * 128 + c * 16)), src, ok ? 16 : 0);
        }
        CP_COMMIT();
    };

    load_stage(0, 0);

    for (int t = 0; t < NT; t++) {
        const int buf = t & 1;
        if (t + 1 < NT) {
            load_stage(t + 1, buf ^ 1);
            CP_WAIT(1);
        } else {
            CP_WAIT(0);
        }
        __syncthreads();

        const uint32_t abase = sbase + (uint32_t)buf * STAGEB;
        const uint32_t bbase = abase + ABYTES;
#pragma unroll
        for (int ks = 0; ks < 4; ks++) {
            uint32_t ra[MI][4], rb[NI][2];
#pragma unroll
            for (int mi = 0; mi < MI; mi++) {
                int row = wm * (MI * 16) + mi * 16 + (lane & 15);
                uint32_t off = (uint32_t)(row * 128 + ks * 32 + (lane >> 4) * 16);
                ldsm_x4(ra[mi], abase + swz(off));
            }
#pragma unroll
            for (int ni = 0; ni < NI; ni++) {
                int l16 = lane & 15;
                int row = wn * 32 + ni * 8 + (l16 & 7);
                uint32_t off = (uint32_t)(row * 128 + ks * 32 + ((l16 >> 3) & 1) * 16);
                ldsm_x2(rb[ni], bbase + swz(off));
            }
#pragma unroll
            for (int mi = 0; mi < MI; mi++)
#pragma unroll
                for (int ni = 0; ni < NI; ni++)
                    mma_bf16(acc[mi][ni], ra[mi], rb[ni]);
        }
        __syncthreads();
    }

    if constexpr (EPI == 0) {
        // direct fp32 epilogue (32B-segment stores; d_out)
#pragma unroll
        for (int mi = 0; mi < MI; mi++) {
            int rb0 = m0 + wm * (MI * 16) + mi * 16 + (lane >> 2);
#pragma unroll
            for (int ni = 0; ni < NI; ni++) {
                int cb = n0 + wn * 32 + ni * 8 + (lane & 3) * 2;
#pragma unroll
                for (int half = 0; half < 2; half++) {
                    int gm = rb0 + half * 8;
                    if (gm >= Mrows) continue;
                    float* crow = Cf + (long)gm * ldc;
#pragma unroll
                    for (int e = 0; e < 2; e++) {
                        int gn = cb + e;
                        if (gn >= Nrows) continue;
                        float v = acc[mi][ni][half * 2 + e];
                        if (bias) v += bias[gn];
                        if (relu) v = fmaxf(v, 0.0f);
                        crow[gn] = v;
                    }
                }
            }
        }
    } else {
        // ---- phase 1: stage packed (hi,lo) into smem ----
        uint32_t* stage = (uint32_t*)smem;
#pragma unroll
        for (int mi = 0; mi < MI; mi++) {
            int rl0 = wm * (MI * 16) + mi * 16 + (lane >> 2);
#pragma unroll
            for (int ni = 0; ni < NI; ni++) {
                int cl0 = wn * 32 + ni * 8 + (lane & 3) * 2;
#pragma unroll
                for (int half = 0; half < 2; half++) {
                    int rl = rl0 + half * 8;
#pragma unroll
                    for (int e = 0; e < 2; e++) {
                        int cl = cl0 + e;
                        int gn = n0 + cl;
                        float v = acc[mi][ni][half * 2 + e];
                        if (bias && gn < Nrows) v += bias[gn];
                        if (relu) v = fmaxf(v, 0.0f);
                        stage[rl * SSTR + cl] = pack_hilo(v);
                    }
                }
            }
        }
        __syncthreads();
        // ---- phase 2: coalesced writer ----
        for (int idx = tid; idx < 128 * BN; idx += 256) {
            int r = idx / BN, c = idx - r * BN;
            int gm = m0 + r, gn = n0 + c;
            if (gm >= Mrows || gn >= Nrows) continue;
            uint32_t pk = stage[r * SSTR + c];
            __nv_bfloat16 hi = bits_bf((uint16_t)(pk & 0xFFFF));
            __nv_bfloat16 lo = bits_bf((uint16_t)(pk >> 16));
            if constexpr (EPI == 1) {
                __nv_bfloat16* d = S0 + (long)gm * KT_R;
                d[gn] = hi; d[REDUC + gn] = hi; d[2 * REDUC + gn] = lo;
            } else if constexpr (EPI == 2) {
                if (gn < 300) {
                    Cf[(long)gm * ldc + gn] = __bfloat162float(hi) + __bfloat162float(lo);
                } else if (gn < 450) {
                    int k = gn - 300;
                    __nv_bfloat16* d = S0 + (long)gm * KT_N;
                    d[k] = hi; d[HID + k] = hi; d[2 * HID + k] = lo;
                } else {
                    int k = gn - 450;
                    __nv_bfloat16* d = S1 + (long)gm * KT_N;
                    d[k] = hi; d[HID + k] = hi; d[2 * HID + k] = lo;
                }
            } else {  // EPI == 3 : B-layout [hi|lo|hi], row remap
                int p = gn / 150, k = gn - p * 150;
                __nv_bfloat16* d = S0 + ((long)gm * 4 + p) * KT_N;
                d[k] = hi; d[HID + k] = lo; d[2 * HID + k] = hi;
            }
        }
    }
}

// ---------------------------------------------------------------------------
// Prep: concat projection weights (fp32), biases, biaffine bias column
// ---------------------------------------------------------------------------
__global__ void prep_kernel(const float* __restrict__ Wap, const float* __restrict__ bap,
                            const float* __restrict__ Wop, const float* __restrict__ bop,
                            const float* __restrict__ Wap2, const float* __restrict__ bap2,
                            const float* __restrict__ Wop2, const float* __restrict__ bop2,
                            const float* __restrict__ Wbi)
{
    int i = blockIdx.x * blockDim.x + threadIdx.x;
    if (i < PROJN * REDUC) {
        int n = i / REDUC, k = i % REDUC;
        const float* src = (n < 150) ? Wap : (n < 300) ? Wop : (n < 450) ? Wap2 : Wop2;
        g_WprojF[i] = src[(n % 150) * REDUC + k];
    }
    if (i < PROJN) {
        const float* sb = (i < 150) ? bap : (i < 300) ? bop : (i < 450) ? bap2 : bop2;
        g_bproj[i] = sb[i % 150];
        g_bbi[i]   = Wbi[i * 151 + 150];
    }
}

// ---------------------------------------------------------------------------
// fp32 -> concatenated split-bf16 rows (weights only).  grid.x = row.
// B-layout: [hi(K) | lo(K) | hi(K) | 0...]
// ---------------------------------------------------------------------------
__global__ void conv_cat_w(const float* __restrict__ src, int sld,
                           __nv_bfloat16* __restrict__ dst, int KT, int K)
{
    long r = blockIdx.x;
    const float* s = src + r * (long)sld;
    __nv_bfloat16* d = dst + r * (long)KT;
    for (int k = threadIdx.x; k < KT; k += blockDim.x) {
        float v = 0.0f;
        bool want_lo = false;
        if (k < K) v = s[k];
        else if (k < 2 * K) { v = s[k - K]; want_lo = true; }
        else if (k < 3 * K) v = s[k - 2 * K];
        __nv_bfloat16 hi = __float2bfloat16(v);
        d[k] = want_lo ? __float2bfloat16(v - __bfloat162float(hi)) : hi;
    }
}

// ---------------------------------------------------------------------------
// Pool subwords + POS embed -> A-layout h [m, KT_H]
// ---------------------------------------------------------------------------
__global__ void pool_embed_bf(const float* __restrict__ bert,
                              const int* __restrict__ positions,
                              const int* __restrict__ postag,
                              const float* __restrict__ embed)
{
    int m = blockIdx.x;
    int b = m / L_;
    __shared__ int s_start, s_end, s_tag;
    if (threadIdx.x == 0) {
        s_start = positions[m * 2 + 0];
        s_end   = positions[m * 2 + 1];
        s_tag   = postag[m];
    }
    __syncthreads();
    const int start = s_start, end = s_end, tag = s_tag;
    const float inv = 1.0f / (float)(end - start + 1);
    const float* bb = bert + (long)b * S_ * D_;
    __nv_bfloat16* d = g_hbf + (long)m * KT_H;
    for (int f = threadIdx.x; f < FEAT; f += blockDim.x) {
        float v;
        if (f < POSD) {
            v = embed[tag * POSD + f];
        } else {
            int dd = f - POSD;
            float s = 0.0f;
            for (int si = start; si <= end; si++) s += bb[(long)si * D_ + dd];
            v = s * inv;
        }
        __nv_bfloat16 hi = __float2bfloat16(v);
        float lo = v - __bfloat162float(hi);
        d[f]            = hi;
        d[FEAT + f]     = hi;
        d[2 * FEAT + f] = __float2bfloat16(lo);
    }
    for (int f = 3 * FEAT + threadIdx.x; f < KT_H; f += blockDim.x)
        d[f] = __float2bfloat16(0.0f);
}

// ---------------------------------------------------------------------------
// Tag heads (fp32, tiny) -- g_proj is [M, 300]
// ---------------------------------------------------------------------------
__global__ void tag_kernel(const float* __restrict__ Wap, const float* __restrict__ bap,
                           const float* __restrict__ Wop, const float* __restrict__ bop,
                           float* __restrict__ out)
{
    int i = blockIdx.x * blockDim.x + threadIdx.x;
    if (i >= M_ * 2 * TAGS) return;
    int m = i / (2 * TAGS);
    int r = i % (2 * TAGS);
    int t = r % TAGS;
    bool is_op = (r >= TAGS);
    const float* a = g_proj + (long)m * 300 + (is_op ? 150 : 0);
    const float* w = (is_op ? Wop : Wap) + t * HID;
    float s = (is_op ? bop : bap)[t];
#pragma unroll 5
    for (int k = 0; k < HID; k++) s += a[k] * w[k];
    out[(is_op ? (long)M_ * TAGS : 0l) + (long)m * TAGS + t] = s;
}

// ---------------------------------------------------------------------------
// kernel_launch
// ---------------------------------------------------------------------------
template <typename T_>
static T_* sym_addr(const void* symbol) {
    void* p = nullptr;
    cudaGetSymbolAddress(&p, symbol);
    return (T_*)p;
}

#define SMEM128_PIPE  65536                 // 2 * (16K A + 16K B)
#define SMEM128_STAGE 69632                 // 128 * 136 * 4
#define SMEM64_PIPE   49152                 // 2 * (16K A + 8K B)

extern "C" void kernel_launch(void* const* d_in, const int* in_sizes, int n_in,
                              void* d_out, int out_size)
{
    const float* bert      = (const float*)d_in[0];
    const int*   positions = (const int*)  d_in[1];
    const int*   postag    = (const int*)  d_in[2];
    const float* embed     = (const float*)d_in[3];
    const float* W_reduc   = (const float*)d_in[4];
    const float* b_reduc   = (const float*)d_in[5];
    const float* W_ap      = (const float*)d_in[6];
    const float* b_ap      = (const float*)d_in[7];
    const float* W_op      = (const float*)d_in[8];
    const float* b_op      = (const float*)d_in[9];
    const float* W_ap2     = (const float*)d_in[10];
    const float* b_ap2     = (const float*)d_in[11];
    const float* W_op2     = (const float*)d_in[12];
    const float* b_op2     = (const float*)d_in[13];
    const float* W_aptag   = (const float*)d_in[14];
    const float* b_aptag   = (const float*)d_in[15];
    const float* W_optag   = (const float*)d_in[16];
    const float* b_optag   = (const float*)d_in[17];
    const float* W_bi      = (const float*)d_in[18];
    float* out = (float*)d_out;

    __nv_bfloat16* p_hbf      = sym_addr<__nv_bfloat16>(g_hbf);
    __nv_bfloat16* p_Wr_bf    = sym_addr<__nv_bfloat16>(g_Wr_bf);
    __nv_bfloat16* p_reduc_bf = sym_addr<__nv_bfloat16>(g_reduc_bf);
    float*         p_WprojF   = sym_addr<float>(g_WprojF);
    __nv_bfloat16* p_Wp_bf    = sym_addr<__nv_bfloat16>(g_Wp_bf);
    float*         p_bproj    = sym_addr<float>(g_bproj);
    float*         p_bbi      = sym_addr<float>(g_bbi);
    float*         p_proj     = sym_addr<float>(g_proj);
    __nv_bfloat16* p_apn_bf   = sym_addr<__nv_bfloat16>(g_apn_bf);
    __nv_bfloat16* p_opn_bf   = sym_addr<__nv_bfloat16>(g_opn_bf);
    __nv_bfloat16* p_Wbi_bf   = sym_addr<__nv_bfloat16>(g_Wbi_bf);
    __nv_bfloat16* p_aff_bf   = sym_addr<__nv_bfloat16>(g_aff_bf);

    cudaFuncSetAttribute(gemm_mma<128,0>, cudaFuncAttributeMaxDynamicSharedMemorySize, SMEM128_PIPE);
    cudaFuncSetAttribute(gemm_mma<64,0>,  cudaFuncAttributeMaxDynamicSharedMemorySize, SMEM64_PIPE);
    cudaFuncSetAttribute(gemm_mma<128,1>, cudaFuncAttributeMaxDynamicSharedMemorySize, SMEM128_STAGE);
    cudaFuncSetAttribute(gemm_mma<64,1>,  cudaFuncAttributeMaxDynamicSharedMemorySize, SMEM64_PIPE);
    cudaFuncSetAttribute(gemm_mma<128,2>, cudaFuncAttributeMaxDynamicSharedMemorySize, SMEM128_STAGE);
    cudaFuncSetAttribute(gemm_mma<128,3>, cudaFuncAttributeMaxDynamicSharedMemorySize, SMEM128_STAGE);

    // 1. weight prep + conversions (B-layout [hi|lo|hi])
    prep_kernel<<<(PROJN * REDUC + 255) / 256, 256>>>(
        W_ap, b_ap, W_op, b_op, W_ap2, b_ap2, W_op2, b_op2, W_bi);
    conv_cat_w<<<REDUC, 128>>>(W_reduc, FEAT, p_Wr_bf, KT_H, FEAT);
    conv_cat_w<<<PROJN, 128>>>(p_WprojF, REDUC, p_Wp_bf, KT_R, REDUC);
    conv_cat_w<<<PROJN, 128>>>(W_bi, 151, p_Wbi_bf, KT_N, HID);

    // 2. pool + embed -> A-layout h [hi|hi|lo]
    pool_embed_bf<<<M_, 256>>>(bert, positions, postag, embed);

    // 3. reduc GEMM -> split-bf16 A-layout directly   NT=39, tiles 3x128 + 1x64
    gemm_mma<128,1><<<dim3(3, M_ / 128, 1), 256, SMEM128_STAGE>>>(
        p_hbf, KT_H, 0, M_, p_Wr_bf, KT_H, 0, REDUC,
        b_reduc, nullptr, 0, 0, p_reduc_bf, nullptr, KT_H / 64, 0, 0);
    gemm_mma<64,1><<<dim3(1, M_ / 128, 1), 256, SMEM64_PIPE>>>(
        p_hbf, KT_H, 0, M_, p_Wr_bf, KT_H, 0, REDUC,
        b_reduc, nullptr, 0, 0, p_reduc_bf, nullptr, KT_H / 64, 384, 0);

    // 4. fused projections + relu: fp32 tag cols + split apn/opn   NT=19
    gemm_mma<128,2><<<dim3(5, M_ / 128, 1), 256, SMEM128_STAGE>>>(
        p_reduc_bf, KT_R, 0, M_, p_Wp_bf, KT_R, 0, PROJN,
        p_bproj, p_proj, 300, 0, p_apn_bf, p_opn_bf, KT_R / 64, 0, 1);

    // 5. affine GEMM -> split-bf16 B-layout [102400,150]   NT=8
    gemm_mma<128,3><<<dim3(5, M_ / 128, 1), 256, SMEM128_STAGE>>>(
        p_apn_bf, KT_N, 0, M_, p_Wbi_bf, KT_N, 0, PROJN,
        p_bbi, nullptr, 0, 0, p_aff_bf, nullptr, KT_N / 64, 0, 0);

    // 6. tag heads -> out[0 : 256000]
    tag_kernel<<<(M_ * 10 + 255) / 256, 256>>>(W_aptag, b_aptag, W_optag, b_optag, out);

    // 7. triplet per batch: C[l2, l1*4+p] = op_node[l2,:] . affine[l1*4+p,:]
    //    NT=8, tiles 6x128 + 1x64
    gemm_mma<128,0><<<dim3(6, (L_ + 127) / 128, B_), 256, SMEM128_PIPE>>>(
        p_opn_bf, KT_N, (long)L_ * KT_N, L_,
        p_aff_bf, KT_N, (long)800 * KT_N, 800,
        nullptr, out + 2l * M_ * TAGS, 800, 160000l,
        nullptr, nullptr, KT_N / 64, 0, 0);
    gemm_mma<64,0><<<dim3(1, (L_ + 127) / 128, B_), 256, SMEM64_PIPE>>>(
        p_opn_bf, KT_N, (long)L_ * KT_N, L_,
        p_aff_bf, KT_N, (long)800 * KT_N, 800,
        nullptr, out + 2l * M_ * TAGS, 800, 160000l,
        nullptr, nullptr, KT_N / 64, 768, 0);
}